// round 13
// baseline (speedup 1.0000x reference)
#include <cuda_runtime.h>
#include <cuda_fp16.h>
#include <cstdint>

#define NUM_USERS  100000
#define NUM_ITEMS  50000
#define NUM_BRANDS 1000
#define NTOT       (NUM_USERS + NUM_ITEMS + NUM_BRANDS)   // 151000
#define DIM        64
#define DCONT      384
#define KDIM       (DIM + DCONT)                          // 448
#define NDF        (NTOT * DIM)
#define ND4        (NDF / 4)
#define ND8        (NDF / 8)
#define UD4        (NUM_USERS * DIM / 4)
#define ID4        ((NUM_ITEMS * DIM) / 4)
#define UD8        (NUM_USERS * DIM / 8)
#define BR8        ((NUM_BRANDS * DIM) / 8)
#define INIT8      (UD8 + BR8)
#define ECHO4      (UD4 + ID4)                             // 2,400,000
#define CAP        96                                      // per-row segment
                   // deg ~ Binom(4.8M, 1/151K): mean 31.8, sigma 5.6;
                   // P(deg > 96) ~ 1e-24 * NTOT -> never overflows.

#define BM 128
#define BN 64
#define BK 16
#define GEMM_BLOCKS ((NUM_ITEMS + BM - 1) / BM)            // 391

// Scratch
__device__ uint4 g_hA[ND8];   // ego (fp16 x8 per uint4)
__device__ uint4 g_hB[ND8];   // y1
__device__ uint4 g_hC[ND8];   // y2
__device__ int   g_cnt[NTOT];              // per-row fill cursor / degree
__device__ int2  g_ecv[(size_t)NTOT * CAP]; // padded per-row edge segments

// ---------- packed f32x2 helpers ----------
__device__ __forceinline__ unsigned long long pack2(float lo, float hi) {
    unsigned long long r;
    asm("mov.b64 %0, {%1, %2};" : "=l"(r) : "f"(lo), "f"(hi));
    return r;
}
__device__ __forceinline__ void fma2(unsigned long long& d,
                                     unsigned long long a,
                                     unsigned long long b) {
    asm("fma.rn.f32x2 %0, %1, %2, %0;" : "+l"(d) : "l"(a), "l"(b));
}
__device__ __forceinline__ float2 unpack2(unsigned long long v) {
    float2 r;
    asm("mov.b64 {%0, %1}, %2;" : "=f"(r.x), "=f"(r.y) : "l"(v));
    return r;
}

__device__ __forceinline__ uint4 f8_to_h8(const float* o) {
    uint4 r;
    __half2* h = reinterpret_cast<__half2*>(&r);
    h[0] = __floats2half2_rn(o[0], o[1]);
    h[1] = __floats2half2_rn(o[2], o[3]);
    h[2] = __floats2half2_rn(o[4], o[5]);
    h[3] = __floats2half2_rn(o[6], o[7]);
    return r;
}

// ---------------------------------------------------------------------------
// GEMM device path (R8, unchanged)
// ---------------------------------------------------------------------------
__device__ void gemm_path(int gblk, int tid,
                          const float* __restrict__ id_emb,
                          const float* __restrict__ content,
                          const float* __restrict__ W,
                          const float* __restrict__ bias,
                          uint4* __restrict__ hA,
                          float* smem_raw) {
    float (*As)[BM + 4] = reinterpret_cast<float (*)[BM + 4]>(smem_raw);
    float (*Ws)[BN + 4] = reinterpret_cast<float (*)[BN + 4]>(smem_raw + BK * (BM + 4));

    const int tx = tid & 7;
    const int ty = tid >> 3;
    const int block_row = gblk * BM;

    unsigned long long acc2[2][8];
#pragma unroll
    for (int p = 0; p < 2; p++)
#pragma unroll
        for (int j = 0; j < 8; j++) acc2[p][j] = 0ULL;

    for (int k0 = 0; k0 < KDIM; k0 += BK) {
#pragma unroll
        for (int i = 0; i < 2; i++) {
            int lin = tid + i * 256;
            int r = lin >> 2;
            int kq = (lin & 3) * 4;
            int gr = block_row + r;
            float4 v = make_float4(0.f, 0.f, 0.f, 0.f);
            if (gr < NUM_ITEMS) {
                int gk = k0 + kq;
                v = (gk < DIM)
                  ? *reinterpret_cast<const float4*>(id_emb + (size_t)gr * DIM + gk)
                  : *reinterpret_cast<const float4*>(content + (size_t)gr * DCONT + (gk - DIM));
            }
            As[kq + 0][r] = v.x;
            As[kq + 1][r] = v.y;
            As[kq + 2][r] = v.z;
            As[kq + 3][r] = v.w;
        }
        {
            int j = tid >> 2;
            int kq = (tid & 3) * 4;
            float4 v = *reinterpret_cast<const float4*>(W + (size_t)j * KDIM + k0 + kq);
            Ws[kq + 0][j] = v.x;
            Ws[kq + 1][j] = v.y;
            Ws[kq + 2][j] = v.z;
            Ws[kq + 3][j] = v.w;
        }
        __syncthreads();

#pragma unroll
        for (int k = 0; k < BK; k++) {
            float4 a4 = *reinterpret_cast<const float4*>(&As[k][ty * 4]);
            unsigned long long a2[2];
            a2[0] = pack2(a4.x, a4.y);
            a2[1] = pack2(a4.z, a4.w);
            float4 w0 = *reinterpret_cast<const float4*>(&Ws[k][tx * 8]);
            float4 w1 = *reinterpret_cast<const float4*>(&Ws[k][tx * 8 + 4]);
            unsigned long long wb[8];
            wb[0] = pack2(w0.x, w0.x); wb[1] = pack2(w0.y, w0.y);
            wb[2] = pack2(w0.z, w0.z); wb[3] = pack2(w0.w, w0.w);
            wb[4] = pack2(w1.x, w1.x); wb[5] = pack2(w1.y, w1.y);
            wb[6] = pack2(w1.z, w1.z); wb[7] = pack2(w1.w, w1.w);
#pragma unroll
            for (int p = 0; p < 2; p++)
#pragma unroll
                for (int j = 0; j < 8; j++) fma2(acc2[p][j], a2[p], wb[j]);
        }
        __syncthreads();
    }

    float4 b0 = *reinterpret_cast<const float4*>(bias + tx * 8);
    float4 b1 = *reinterpret_cast<const float4*>(bias + tx * 8 + 4);
    float bcol[8] = {b0.x, b0.y, b0.z, b0.w, b1.x, b1.y, b1.z, b1.w};

#pragma unroll
    for (int r = 0; r < 4; r++) {
        int gr = block_row + ty * 4 + r;
        if (gr >= NUM_ITEMS) continue;
        int p = r >> 1;
        float o[8];
#pragma unroll
        for (int j = 0; j < 8; j++) {
            float2 u = unpack2(acc2[p][j]);
            float v = ((r & 1) ? u.y : u.x) + bcol[j];
            o[j] = (v > 0.f) ? v : 0.01f * v;
        }
        hA[(size_t)(NUM_USERS + gr) * 8 + tx] = f8_to_h8(o);
    }
}

// ---------------------------------------------------------------------------
// K1 mega: [0,G) gemm | rest: fp32->fp16 user/brand init (hist eliminated)
// ---------------------------------------------------------------------------
__global__ __launch_bounds__(256)
void mega1_kernel(const float* __restrict__ id_emb,
                  const float* __restrict__ content,
                  const float* __restrict__ W,
                  const float* __restrict__ bias,
                  const float* __restrict__ user_emb,
                  const float* __restrict__ brand,
                  uint4* __restrict__ hA) {
    __shared__ float smem_raw[BK * (BM + 4) + BK * (BN + 4)];
    int b = blockIdx.x;
    int tid = threadIdx.x;

    if (b < GEMM_BLOCKS) {
        gemm_path(b, tid, id_emb, content, W, bias, hA, smem_raw);
        return;
    }
    b -= GEMM_BLOCKS;
    int idx = b * 256 + tid;
    if (idx >= INIT8) return;
    const float* src;
    size_t dst;
    if (idx < UD8) { src = user_emb + (size_t)idx * 8; dst = idx; }
    else {
        src = brand + (size_t)(idx - UD8) * 8;
        dst = (size_t)(NUM_USERS + NUM_ITEMS) * 8 + (idx - UD8);
    }
    float4 f0 = *reinterpret_cast<const float4*>(src);
    float4 f1 = *reinterpret_cast<const float4*>(src + 4);
    float o[8] = {f0.x, f0.y, f0.z, f0.w, f1.x, f1.y, f1.z, f1.w};
    hA[dst] = f8_to_h8(o);
}

// ---------------------------------------------------------------------------
// Direct scatter into fixed-capacity row segments: ONE atomic per edge,
// no hist, no scan, no rowptr. slot = row*CAP + atomicAdd(&cnt[row],1).
// ---------------------------------------------------------------------------
__global__ void scatter_direct_kernel(const int* __restrict__ rows,
                                      const int* __restrict__ cols,
                                      const float* __restrict__ vals, int E,
                                      int* __restrict__ cnt,
                                      long long* __restrict__ ecv) {
    int i = blockIdx.x * blockDim.x + threadIdx.x;
    int base = i * 4;
    if (base + 4 <= E) {
        int4   r = *reinterpret_cast<const int4*>(rows + base);
        int4   c = *reinterpret_cast<const int4*>(cols + base);
        float4 v = *reinterpret_cast<const float4*>(vals + base);
        int p;
        p = atomicAdd(&cnt[r.x], 1);
        ecv[(size_t)r.x * CAP + p] =
            ((long long)__float_as_int(v.x) << 32) | (unsigned int)c.x;
        p = atomicAdd(&cnt[r.y], 1);
        ecv[(size_t)r.y * CAP + p] =
            ((long long)__float_as_int(v.y) << 32) | (unsigned int)c.y;
        p = atomicAdd(&cnt[r.z], 1);
        ecv[(size_t)r.z * CAP + p] =
            ((long long)__float_as_int(v.z) << 32) | (unsigned int)c.z;
        p = atomicAdd(&cnt[r.w], 1);
        ecv[(size_t)r.w * CAP + p] =
            ((long long)__float_as_int(v.w) << 32) | (unsigned int)c.w;
    } else {
        for (int j = base; j < E; j++) {
            int r = rows[j];
            int p = atomicAdd(&cnt[r], 1);
            ecv[(size_t)r * CAP + p] =
                ((long long)__float_as_int(vals[j]) << 32) | (unsigned int)cols[j];
        }
    }
}

// ---------------------------------------------------------------------------
// fp16 CSR SpMM: 8 lanes/row, uint4 per lane, 4-edge unroll (R8 loop),
// bounds from (row*CAP, cnt[row]).
// ---------------------------------------------------------------------------
struct F8acc { float2 a, b, c, d; };

__device__ __forceinline__ void fma_h8(F8acc& acc, float v, uint4 x) {
    const __half2* h = reinterpret_cast<const __half2*>(&x);
    float2 f0 = __half22float2(h[0]);
    float2 f1 = __half22float2(h[1]);
    float2 f2 = __half22float2(h[2]);
    float2 f3 = __half22float2(h[3]);
    acc.a.x = fmaf(v, f0.x, acc.a.x); acc.a.y = fmaf(v, f0.y, acc.a.y);
    acc.b.x = fmaf(v, f1.x, acc.b.x); acc.b.y = fmaf(v, f1.y, acc.b.y);
    acc.c.x = fmaf(v, f2.x, acc.c.x); acc.c.y = fmaf(v, f2.y, acc.c.y);
    acc.d.x = fmaf(v, f3.x, acc.d.x); acc.d.y = fmaf(v, f3.y, acc.d.y);
}

__device__ __forceinline__ F8acc spmm_row_h(const int* __restrict__ cnt,
                                            const int2* __restrict__ ecv,
                                            const uint4* __restrict__ X,
                                            int row, int lane) {
    long long s = (long long)row * CAP;
    long long e = s + __ldg(cnt + row);
    F8acc acc;
    acc.a = make_float2(0.f, 0.f); acc.b = make_float2(0.f, 0.f);
    acc.c = make_float2(0.f, 0.f); acc.d = make_float2(0.f, 0.f);
    long long i = s;
    for (; i + 4 <= e; i += 4) {
        int2 c0 = __ldg(ecv + i),     c1 = __ldg(ecv + i + 1);
        int2 c2 = __ldg(ecv + i + 2), c3 = __ldg(ecv + i + 3);
        uint4 x0 = __ldg(X + (size_t)c0.x * 8 + lane);
        uint4 x1 = __ldg(X + (size_t)c1.x * 8 + lane);
        uint4 x2 = __ldg(X + (size_t)c2.x * 8 + lane);
        uint4 x3 = __ldg(X + (size_t)c3.x * 8 + lane);
        fma_h8(acc, __int_as_float(c0.y), x0);
        fma_h8(acc, __int_as_float(c1.y), x1);
        fma_h8(acc, __int_as_float(c2.y), x2);
        fma_h8(acc, __int_as_float(c3.y), x3);
    }
    for (; i < e; i++) {
        int2 ee = __ldg(ecv + i);
        uint4 xv = __ldg(X + (size_t)ee.x * 8 + lane);
        fma_h8(acc, __int_as_float(ee.y), xv);
    }
    return acc;
}

__device__ __forceinline__ uint4 acc_to_h8(const F8acc& acc) {
    uint4 r;
    __half2* h = reinterpret_cast<__half2*>(&r);
    h[0] = __float22half2_rn(acc.a);
    h[1] = __float22half2_rn(acc.b);
    h[2] = __float22half2_rn(acc.c);
    h[3] = __float22half2_rn(acc.d);
    return r;
}

#define SPMM_BLOCKS_H ((NTOT * 8 + 255) / 256)
#define ECHO_BLOCKS   ((ECHO4 + 255) / 256)

// Layer 1 (+ echo copies folded in — R8 placement, measured best)
__global__ void spmm1_mega_kernel(const int* __restrict__ cnt,
                                  const int2* __restrict__ ecv,
                                  const uint4* __restrict__ X,
                                  uint4* __restrict__ Y,
                                  const float* __restrict__ user_emb,
                                  const float* __restrict__ item_id,
                                  float* __restrict__ out) {
    int b = blockIdx.x;
    int tid = threadIdx.x;
    if (b < SPMM_BLOCKS_H) {
        int g = b * 256 + tid;
        int row = g >> 3;
        int lane = g & 7;
        if (row >= NTOT) return;
        F8acc a = spmm_row_h(cnt, ecv, X, row, lane);
        Y[(size_t)row * 8 + lane] = acc_to_h8(a);
        return;
    }
    b -= SPMM_BLOCKS_H;
    int idx = b * 256 + tid;
    if (idx >= ECHO4) return;
    float4 v = (idx < UD4)
             ? reinterpret_cast<const float4*>(user_emb)[idx]
             : reinterpret_cast<const float4*>(item_id)[idx - UD4];
    reinterpret_cast<float4*>(out)[ND4 + idx] = v;
}

// Layer 2
__global__ void spmm_mid_kernel(const int* __restrict__ cnt,
                                const int2* __restrict__ ecv,
                                const uint4* __restrict__ X,
                                uint4* __restrict__ Y) {
    int g = blockIdx.x * blockDim.x + threadIdx.x;
    int row = g >> 3;
    int lane = g & 7;
    if (row >= NTOT) return;
    F8acc a = spmm_row_h(cnt, ecv, X, row, lane);
    Y[(size_t)row * 8 + lane] = acc_to_h8(a);
}

// Layer 3 fused finalize: out = (A + B + C + spmm(C)) * 0.25, fp32 out.
__global__ void spmm_last_kernel(const int* __restrict__ cnt,
                                 const int2* __restrict__ ecv,
                                 const uint4* __restrict__ hA,
                                 const uint4* __restrict__ hB,
                                 const uint4* __restrict__ hC,
                                 float* __restrict__ out) {
    int g = blockIdx.x * blockDim.x + threadIdx.x;
    int row = g >> 3;
    int lane = g & 7;
    if (row >= NTOT) return;
    F8acc a = spmm_row_h(cnt, ecv, hC, row, lane);
    size_t o8 = (size_t)row * 8 + lane;
    uint4 ua = __ldg(hA + o8);
    uint4 ub = __ldg(hB + o8);
    uint4 uc = __ldg(hC + o8);
    const __half2* ha = reinterpret_cast<const __half2*>(&ua);
    const __half2* hb = reinterpret_cast<const __half2*>(&ub);
    const __half2* hc = reinterpret_cast<const __half2*>(&uc);
    float res[8];
    float2* ap = reinterpret_cast<float2*>(&a);
#pragma unroll
    for (int q = 0; q < 4; q++) {
        float2 fa = __half22float2(ha[q]);
        float2 fb = __half22float2(hb[q]);
        float2 fc = __half22float2(hc[q]);
        res[q * 2 + 0] = (fa.x + fb.x + fc.x + ap[q].x) * 0.25f;
        res[q * 2 + 1] = (fa.y + fb.y + fc.y + ap[q].y) * 0.25f;
    }
    size_t base = (size_t)row * DIM + lane * 8;
    *reinterpret_cast<float4*>(out + base)     = make_float4(res[0], res[1], res[2], res[3]);
    *reinterpret_cast<float4*>(out + base + 4) = make_float4(res[4], res[5], res[6], res[7]);
}

// ---------------------------------------------------------------------------
extern "C" void kernel_launch(void* const* d_in, const int* in_sizes, int n_in,
                              void* d_out, int out_size) {
    const int*   edge_row = (const int*)  d_in[0];
    const int*   edge_col = (const int*)  d_in[1];
    const float* edge_val = (const float*)d_in[2];
    const float* user_emb = (const float*)d_in[3];
    const float* item_id  = (const float*)d_in[4];
    const float* brand    = (const float*)d_in[5];
    const float* content  = (const float*)d_in[6];
    const float* fusion_W = (const float*)d_in[7];
    const float* fusion_b = (const float*)d_in[8];
    const int E = in_sizes[0];

    uint4 *hA, *hB, *hC;
    int *cnt;
    int2 *ecv;
    cudaGetSymbolAddress((void**)&hA,  g_hA);
    cudaGetSymbolAddress((void**)&hB,  g_hB);
    cudaGetSymbolAddress((void**)&hC,  g_hC);
    cudaGetSymbolAddress((void**)&cnt, g_cnt);
    cudaGetSymbolAddress((void**)&ecv, g_ecv);

    cudaMemsetAsync(cnt, 0, NTOT * sizeof(int));

    // K1: GEMM + fp16 init (no hist anymore)
    int initBlocks = (INIT8 + 255) / 256;
    mega1_kernel<<<GEMM_BLOCKS + initBlocks, 256>>>(
        item_id, content, fusion_W, fusion_b, user_emb, brand, hA);

    // K2: direct scatter into padded segments (single atomic pass)
    scatter_direct_kernel<<<((E + 3) / 4 + 255) / 256, 256>>>(
        edge_row, edge_col, edge_val, E, cnt, (long long*)ecv);

    // Propagation in fp16 storage, fp32 math
    spmm1_mega_kernel<<<SPMM_BLOCKS_H + ECHO_BLOCKS, 256>>>(
        cnt, ecv, hA, hB, user_emb, item_id, (float*)d_out);
    spmm_mid_kernel<<<SPMM_BLOCKS_H, 256>>>(cnt, ecv, hB, hC);
    spmm_last_kernel<<<SPMM_BLOCKS_H, 256>>>(cnt, ecv, hA, hB, hC,
                                             (float*)d_out);
}

// round 14
// speedup vs baseline: 1.0414x; 1.0414x over previous
#include <cuda_runtime.h>
#include <cuda_fp16.h>
#include <cstdint>

#define NUM_USERS  100000
#define NUM_ITEMS  50000
#define NUM_BRANDS 1000
#define NTOT       (NUM_USERS + NUM_ITEMS + NUM_BRANDS)   // 151000
#define DIM        64
#define DCONT      384
#define KDIM       (DIM + DCONT)                          // 448
#define NDF        (NTOT * DIM)
#define ND4        (NDF / 4)
#define ND8        (NDF / 8)
#define UD4        (NUM_USERS * DIM / 4)
#define ID4        ((NUM_ITEMS * DIM) / 4)
#define UD8        (NUM_USERS * DIM / 8)
#define BR8        ((NUM_BRANDS * DIM) / 8)
#define INIT8      (UD8 + BR8)
#define ECHO4      (UD4 + ID4)                             // 2,400,000
#define EMAX       4800000
#define SCAN_CHUNK 1024
#define SCAN_NBLK  ((NTOT + SCAN_CHUNK - 1) / SCAN_CHUNK)  // 148

#define BM 128
#define BN 64
#define BK 16
#define GEMM_BLOCKS ((NUM_ITEMS + BM - 1) / BM)            // 391

// Scratch: half-precision node feature buffers stored as uint4 (8 halves).
__device__ uint4 g_hA[ND8];   // ego
__device__ uint4 g_hB[ND8];   // y1
__device__ uint4 g_hC[ND8];   // y2
__device__ int   g_rowptr[NTOT + 1];
__device__ int   g_cnt[NTOT];          // hist counts, then cursor for scatter
__device__ int2  g_ecv[EMAX];          // packed (col, val_bits fp32)
__device__ int   g_bsum[SCAN_NBLK];

// ---------- packed f32x2 helpers ----------
__device__ __forceinline__ unsigned long long pack2(float lo, float hi) {
    unsigned long long r;
    asm("mov.b64 %0, {%1, %2};" : "=l"(r) : "f"(lo), "f"(hi));
    return r;
}
__device__ __forceinline__ void fma2(unsigned long long& d,
                                     unsigned long long a,
                                     unsigned long long b) {
    asm("fma.rn.f32x2 %0, %1, %2, %0;" : "+l"(d) : "l"(a), "l"(b));
}
__device__ __forceinline__ float2 unpack2(unsigned long long v) {
    float2 r;
    asm("mov.b64 {%0, %1}, %2;" : "=f"(r.x), "=f"(r.y) : "l"(v));
    return r;
}

__device__ __forceinline__ uint4 f8_to_h8(const float* o) {
    uint4 r;
    __half2* h = reinterpret_cast<__half2*>(&r);
    h[0] = __floats2half2_rn(o[0], o[1]);
    h[1] = __floats2half2_rn(o[2], o[3]);
    h[2] = __floats2half2_rn(o[4], o[5]);
    h[3] = __floats2half2_rn(o[6], o[7]);
    return r;
}

// ---------------------------------------------------------------------------
// GEMM device path (R8, unchanged)
// ---------------------------------------------------------------------------
__device__ void gemm_path(int gblk, int tid,
                          const float* __restrict__ id_emb,
                          const float* __restrict__ content,
                          const float* __restrict__ W,
                          const float* __restrict__ bias,
                          uint4* __restrict__ hA,
                          float* smem_raw) {
    float (*As)[BM + 4] = reinterpret_cast<float (*)[BM + 4]>(smem_raw);
    float (*Ws)[BN + 4] = reinterpret_cast<float (*)[BN + 4]>(smem_raw + BK * (BM + 4));

    const int tx = tid & 7;
    const int ty = tid >> 3;
    const int block_row = gblk * BM;

    unsigned long long acc2[2][8];
#pragma unroll
    for (int p = 0; p < 2; p++)
#pragma unroll
        for (int j = 0; j < 8; j++) acc2[p][j] = 0ULL;

    for (int k0 = 0; k0 < KDIM; k0 += BK) {
#pragma unroll
        for (int i = 0; i < 2; i++) {
            int lin = tid + i * 256;
            int r = lin >> 2;
            int kq = (lin & 3) * 4;
            int gr = block_row + r;
            float4 v = make_float4(0.f, 0.f, 0.f, 0.f);
            if (gr < NUM_ITEMS) {
                int gk = k0 + kq;
                v = (gk < DIM)
                  ? *reinterpret_cast<const float4*>(id_emb + (size_t)gr * DIM + gk)
                  : *reinterpret_cast<const float4*>(content + (size_t)gr * DCONT + (gk - DIM));
            }
            As[kq + 0][r] = v.x;
            As[kq + 1][r] = v.y;
            As[kq + 2][r] = v.z;
            As[kq + 3][r] = v.w;
        }
        {
            int j = tid >> 2;
            int kq = (tid & 3) * 4;
            float4 v = *reinterpret_cast<const float4*>(W + (size_t)j * KDIM + k0 + kq);
            Ws[kq + 0][j] = v.x;
            Ws[kq + 1][j] = v.y;
            Ws[kq + 2][j] = v.z;
            Ws[kq + 3][j] = v.w;
        }
        __syncthreads();

#pragma unroll
        for (int k = 0; k < BK; k++) {
            float4 a4 = *reinterpret_cast<const float4*>(&As[k][ty * 4]);
            unsigned long long a2[2];
            a2[0] = pack2(a4.x, a4.y);
            a2[1] = pack2(a4.z, a4.w);
            float4 w0 = *reinterpret_cast<const float4*>(&Ws[k][tx * 8]);
            float4 w1 = *reinterpret_cast<const float4*>(&Ws[k][tx * 8 + 4]);
            unsigned long long wb[8];
            wb[0] = pack2(w0.x, w0.x); wb[1] = pack2(w0.y, w0.y);
            wb[2] = pack2(w0.z, w0.z); wb[3] = pack2(w0.w, w0.w);
            wb[4] = pack2(w1.x, w1.x); wb[5] = pack2(w1.y, w1.y);
            wb[6] = pack2(w1.z, w1.z); wb[7] = pack2(w1.w, w1.w);
#pragma unroll
            for (int p = 0; p < 2; p++)
#pragma unroll
                for (int j = 0; j < 8; j++) fma2(acc2[p][j], a2[p], wb[j]);
        }
        __syncthreads();
    }

    float4 b0 = *reinterpret_cast<const float4*>(bias + tx * 8);
    float4 b1 = *reinterpret_cast<const float4*>(bias + tx * 8 + 4);
    float bcol[8] = {b0.x, b0.y, b0.z, b0.w, b1.x, b1.y, b1.z, b1.w};

#pragma unroll
    for (int r = 0; r < 4; r++) {
        int gr = block_row + ty * 4 + r;
        if (gr >= NUM_ITEMS) continue;
        int p = r >> 1;
        float o[8];
#pragma unroll
        for (int j = 0; j < 8; j++) {
            float2 u = unpack2(acc2[p][j]);
            float v = ((r & 1) ? u.y : u.x) + bcol[j];
            o[j] = (v > 0.f) ? v : 0.01f * v;
        }
        hA[(size_t)(NUM_USERS + gr) * 8 + tx] = f8_to_h8(o);
    }
}

// ---------------------------------------------------------------------------
// K1 mega: [0,G) gemm | [G,G+H) hist | rest: fp32->fp16 user/brand init
// ---------------------------------------------------------------------------
__global__ __launch_bounds__(256)
void mega1_kernel(const float* __restrict__ id_emb,
                  const float* __restrict__ content,
                  const float* __restrict__ W,
                  const float* __restrict__ bias,
                  const float* __restrict__ user_emb,
                  const float* __restrict__ brand,
                  const int*   __restrict__ rows, int E, int histBlocks,
                  int* __restrict__ cnt,
                  uint4* __restrict__ hA) {
    __shared__ float smem_raw[BK * (BM + 4) + BK * (BN + 4)];
    int b = blockIdx.x;
    int tid = threadIdx.x;

    if (b < GEMM_BLOCKS) {
        gemm_path(b, tid, id_emb, content, W, bias, hA, smem_raw);
        return;
    }
    b -= GEMM_BLOCKS;
    if (b < histBlocks) {
        int base = (b * 256 + tid) * 4;
        if (base + 4 <= E) {
            int4 r = *reinterpret_cast<const int4*>(rows + base);
            atomicAdd(&cnt[r.x], 1);
            atomicAdd(&cnt[r.y], 1);
            atomicAdd(&cnt[r.z], 1);
            atomicAdd(&cnt[r.w], 1);
        } else {
            for (int j = base; j < E; j++) atomicAdd(&cnt[rows[j]], 1);
        }
        return;
    }
    b -= histBlocks;
    int idx = b * 256 + tid;
    if (idx >= INIT8) return;
    const float* src;
    size_t dst;
    if (idx < UD8) { src = user_emb + (size_t)idx * 8; dst = idx; }
    else {
        src = brand + (size_t)(idx - UD8) * 8;
        dst = (size_t)(NUM_USERS + NUM_ITEMS) * 8 + (idx - UD8);
    }
    float4 f0 = *reinterpret_cast<const float4*>(src);
    float4 f1 = *reinterpret_cast<const float4*>(src + 4);
    float o[8] = {f0.x, f0.y, f0.z, f0.w, f1.x, f1.y, f1.z, f1.w};
    hA[dst] = f8_to_h8(o);
}

// ---------------------------------------------------------------------------
// CSR scan
// ---------------------------------------------------------------------------
__global__ void scan_partial_kernel(const int* __restrict__ cnt,
                                    int* __restrict__ bsum) {
    __shared__ int s[256];
    int b = blockIdx.x, t = threadIdx.x;
    int base = b * SCAN_CHUNK + t * 4;
    int v = 0;
#pragma unroll
    for (int j = 0; j < 4; j++) {
        int idx = base + j;
        if (idx < NTOT) v += cnt[idx];
    }
    s[t] = v;
    __syncthreads();
    for (int off = 128; off > 0; off >>= 1) {
        if (t < off) s[t] += s[t + off];
        __syncthreads();
    }
    if (t == 0) bsum[b] = s[0];
}

__global__ void write_rowptr_kernel(const int* __restrict__ cnt,
                                    const int* __restrict__ bsum,
                                    int* __restrict__ rp,
                                    int* __restrict__ cur, int E) {
    __shared__ int sb[256];
    __shared__ int s[256];
    int b = blockIdx.x, t = threadIdx.x;

    int bv = (t < SCAN_NBLK) ? bsum[t] : 0;
    sb[t] = bv;
    __syncthreads();
    for (int off = 1; off < 256; off <<= 1) {
        int tmp = (t >= off) ? sb[t - off] : 0;
        __syncthreads();
        sb[t] += tmp;
        __syncthreads();
    }
    int boff_b = sb[b] - bsum[b];
    __syncthreads();

    int base = b * SCAN_CHUNK + t * 4;
    int loc4[4];
    int v = 0;
#pragma unroll
    for (int j = 0; j < 4; j++) {
        int idx = base + j;
        loc4[j] = (idx < NTOT) ? cnt[idx] : 0;
        v += loc4[j];
    }
    s[t] = v;
    __syncthreads();
    for (int off = 1; off < 256; off <<= 1) {
        int tmp = (t >= off) ? s[t - off] : 0;
        __syncthreads();
        s[t] += tmp;
        __syncthreads();
    }
    int run = s[t] - v + boff_b;
#pragma unroll
    for (int j = 0; j < 4; j++) {
        int idx = base + j;
        if (idx < NTOT) { rp[idx] = run; cur[idx] = run; }
        run += loc4[j];
    }
    if (b == 0 && t == 0) rp[NTOT] = E;
}

// Scatter with atomic cursor, 4 edges/thread (R8-measured best).
__global__ void scatter_kernel(const int* __restrict__ rows,
                               const int* __restrict__ cols,
                               const float* __restrict__ vals, int E,
                               int* __restrict__ cur,
                               long long* __restrict__ ecv) {
    int i = blockIdx.x * blockDim.x + threadIdx.x;
    int base = i * 4;
    if (base + 4 <= E) {
        int4   r = *reinterpret_cast<const int4*>(rows + base);
        int4   c = *reinterpret_cast<const int4*>(cols + base);
        float4 v = *reinterpret_cast<const float4*>(vals + base);
        int p;
        p = atomicAdd(&cur[r.x], 1);
        ecv[p] = ((long long)__float_as_int(v.x) << 32) | (unsigned int)c.x;
        p = atomicAdd(&cur[r.y], 1);
        ecv[p] = ((long long)__float_as_int(v.y) << 32) | (unsigned int)c.y;
        p = atomicAdd(&cur[r.z], 1);
        ecv[p] = ((long long)__float_as_int(v.z) << 32) | (unsigned int)c.z;
        p = atomicAdd(&cur[r.w], 1);
        ecv[p] = ((long long)__float_as_int(v.w) << 32) | (unsigned int)c.w;
    } else {
        for (int j = base; j < E; j++) {
            int p = atomicAdd(&cur[rows[j]], 1);
            ecv[p] = ((long long)__float_as_int(vals[j]) << 32) | (unsigned int)cols[j];
        }
    }
}

// ---------------------------------------------------------------------------
// fp16 CSR SpMM: 8 lanes/row, uint4 per lane, 4-edge unroll,
// packed fma.rn.f32x2 accumulation (halves FFMA instruction count).
// ---------------------------------------------------------------------------
struct F8acc { float2 a, b, c, d; };

// acc[0..3] are packed f32x2 accumulators covering 8 dims.
__device__ __forceinline__ void fma_h8_x2(unsigned long long& a0,
                                          unsigned long long& a1,
                                          unsigned long long& a2,
                                          unsigned long long& a3,
                                          unsigned long long v2, uint4 x) {
    const __half2* h = reinterpret_cast<const __half2*>(&x);
    float2 f0 = __half22float2(h[0]);
    float2 f1 = __half22float2(h[1]);
    float2 f2 = __half22float2(h[2]);
    float2 f3 = __half22float2(h[3]);
    fma2(a0, pack2(f0.x, f0.y), v2);
    fma2(a1, pack2(f1.x, f1.y), v2);
    fma2(a2, pack2(f2.x, f2.y), v2);
    fma2(a3, pack2(f3.x, f3.y), v2);
}

__device__ __forceinline__ F8acc spmm_row_h(const int* __restrict__ rp,
                                            const int2* __restrict__ ecv,
                                            const uint4* __restrict__ X,
                                            int row, int lane) {
    int s = __ldg(rp + row), e = __ldg(rp + row + 1);
    unsigned long long a0 = 0ULL, a1 = 0ULL, a2 = 0ULL, a3 = 0ULL;
    int i = s;
    for (; i + 4 <= e; i += 4) {
        int2 c0 = __ldg(ecv + i),     c1 = __ldg(ecv + i + 1);
        int2 c2 = __ldg(ecv + i + 2), c3 = __ldg(ecv + i + 3);
        uint4 x0 = __ldg(X + (size_t)c0.x * 8 + lane);
        uint4 x1 = __ldg(X + (size_t)c1.x * 8 + lane);
        uint4 x2 = __ldg(X + (size_t)c2.x * 8 + lane);
        uint4 x3 = __ldg(X + (size_t)c3.x * 8 + lane);
        float v0 = __int_as_float(c0.y), v1 = __int_as_float(c1.y);
        float v2 = __int_as_float(c2.y), v3 = __int_as_float(c3.y);
        fma_h8_x2(a0, a1, a2, a3, pack2(v0, v0), x0);
        fma_h8_x2(a0, a1, a2, a3, pack2(v1, v1), x1);
        fma_h8_x2(a0, a1, a2, a3, pack2(v2, v2), x2);
        fma_h8_x2(a0, a1, a2, a3, pack2(v3, v3), x3);
    }
    for (; i < e; i++) {
        int2 ee = __ldg(ecv + i);
        uint4 xv = __ldg(X + (size_t)ee.x * 8 + lane);
        float v = __int_as_float(ee.y);
        fma_h8_x2(a0, a1, a2, a3, pack2(v, v), xv);
    }
    F8acc acc;
    acc.a = unpack2(a0);
    acc.b = unpack2(a1);
    acc.c = unpack2(a2);
    acc.d = unpack2(a3);
    return acc;
}

__device__ __forceinline__ uint4 acc_to_h8(const F8acc& acc) {
    uint4 r;
    __half2* h = reinterpret_cast<__half2*>(&r);
    h[0] = __float22half2_rn(acc.a);
    h[1] = __float22half2_rn(acc.b);
    h[2] = __float22half2_rn(acc.c);
    h[3] = __float22half2_rn(acc.d);
    return r;
}

#define SPMM_BLOCKS_H ((NTOT * 8 + 255) / 256)
#define ECHO_BLOCKS   ((ECHO4 + 255) / 256)

// Layer 1 (+ echo copies folded in — R8 placement, measured best)
__global__ __launch_bounds__(256, 6)
void spmm1_mega_kernel(const int* __restrict__ rp,
                       const int2* __restrict__ ecv,
                       const uint4* __restrict__ X,
                       uint4* __restrict__ Y,
                       const float* __restrict__ user_emb,
                       const float* __restrict__ item_id,
                       float* __restrict__ out) {
    int b = blockIdx.x;
    int tid = threadIdx.x;
    if (b < SPMM_BLOCKS_H) {
        int g = b * 256 + tid;
        int row = g >> 3;
        int lane = g & 7;
        if (row >= NTOT) return;
        F8acc a = spmm_row_h(rp, ecv, X, row, lane);
        Y[(size_t)row * 8 + lane] = acc_to_h8(a);
        return;
    }
    b -= SPMM_BLOCKS_H;
    int idx = b * 256 + tid;
    if (idx >= ECHO4) return;
    float4 v = (idx < UD4)
             ? reinterpret_cast<const float4*>(user_emb)[idx]
             : reinterpret_cast<const float4*>(item_id)[idx - UD4];
    reinterpret_cast<float4*>(out)[ND4 + idx] = v;
}

// Layer 2
__global__ __launch_bounds__(256, 6)
void spmm_mid_kernel(const int* __restrict__ rp,
                     const int2* __restrict__ ecv,
                     const uint4* __restrict__ X,
                     uint4* __restrict__ Y) {
    int g = blockIdx.x * blockDim.x + threadIdx.x;
    int row = g >> 3;
    int lane = g & 7;
    if (row >= NTOT) return;
    F8acc a = spmm_row_h(rp, ecv, X, row, lane);
    Y[(size_t)row * 8 + lane] = acc_to_h8(a);
}

// Layer 3 fused finalize: out = (A + B + C + spmm(C)) * 0.25, fp32 out.
__global__ __launch_bounds__(256, 6)
void spmm_last_kernel(const int* __restrict__ rp,
                      const int2* __restrict__ ecv,
                      const uint4* __restrict__ hA,
                      const uint4* __restrict__ hB,
                      const uint4* __restrict__ hC,
                      float* __restrict__ out) {
    int g = blockIdx.x * blockDim.x + threadIdx.x;
    int row = g >> 3;
    int lane = g & 7;
    if (row >= NTOT) return;
    F8acc a = spmm_row_h(rp, ecv, hC, row, lane);
    size_t o8 = (size_t)row * 8 + lane;
    uint4 ua = __ldg(hA + o8);
    uint4 ub = __ldg(hB + o8);
    uint4 uc = __ldg(hC + o8);
    const __half2* ha = reinterpret_cast<const __half2*>(&ua);
    const __half2* hb = reinterpret_cast<const __half2*>(&ub);
    const __half2* hc = reinterpret_cast<const __half2*>(&uc);
    float res[8];
    float2* ap = reinterpret_cast<float2*>(&a);
#pragma unroll
    for (int q = 0; q < 4; q++) {
        float2 fa = __half22float2(ha[q]);
        float2 fb = __half22float2(hb[q]);
        float2 fc = __half22float2(hc[q]);
        res[q * 2 + 0] = (fa.x + fb.x + fc.x + ap[q].x) * 0.25f;
        res[q * 2 + 1] = (fa.y + fb.y + fc.y + ap[q].y) * 0.25f;
    }
    size_t base = (size_t)row * DIM + lane * 8;
    *reinterpret_cast<float4*>(out + base)     = make_float4(res[0], res[1], res[2], res[3]);
    *reinterpret_cast<float4*>(out + base + 4) = make_float4(res[4], res[5], res[6], res[7]);
}

// ---------------------------------------------------------------------------
extern "C" void kernel_launch(void* const* d_in, const int* in_sizes, int n_in,
                              void* d_out, int out_size) {
    const int*   edge_row = (const int*)  d_in[0];
    const int*   edge_col = (const int*)  d_in[1];
    const float* edge_val = (const float*)d_in[2];
    const float* user_emb = (const float*)d_in[3];
    const float* item_id  = (const float*)d_in[4];
    const float* brand    = (const float*)d_in[5];
    const float* content  = (const float*)d_in[6];
    const float* fusion_W = (const float*)d_in[7];
    const float* fusion_b = (const float*)d_in[8];
    const int E = in_sizes[0];

    uint4 *hA, *hB, *hC;
    int *rp, *cnt, *bsum;
    int2 *ecv;
    cudaGetSymbolAddress((void**)&hA,   g_hA);
    cudaGetSymbolAddress((void**)&hB,   g_hB);
    cudaGetSymbolAddress((void**)&hC,   g_hC);
    cudaGetSymbolAddress((void**)&rp,   g_rowptr);
    cudaGetSymbolAddress((void**)&cnt,  g_cnt);
    cudaGetSymbolAddress((void**)&ecv,  g_ecv);
    cudaGetSymbolAddress((void**)&bsum, g_bsum);

    cudaMemsetAsync(cnt, 0, NTOT * sizeof(int));

    // K1: GEMM + hist + fp16 init
    int histBlocks = ((E + 3) / 4 + 255) / 256;
    int initBlocks = (INIT8 + 255) / 256;
    mega1_kernel<<<GEMM_BLOCKS + histBlocks + initBlocks, 256>>>(
        item_id, content, fusion_W, fusion_b, user_emb, brand,
        edge_row, E, histBlocks, cnt, hA);

    scan_partial_kernel<<<SCAN_NBLK, 256>>>(cnt, bsum);
    write_rowptr_kernel<<<SCAN_NBLK, 256>>>(cnt, bsum, rp, cnt, E);
    scatter_kernel<<<((E + 3) / 4 + 255) / 256, 256>>>(
        edge_row, edge_col, edge_val, E, cnt, (long long*)ecv);

    // Propagation in fp16 storage, fp32 math (packed f32x2 FMA)
    spmm1_mega_kernel<<<SPMM_BLOCKS_H + ECHO_BLOCKS, 256>>>(
        rp, ecv, hA, hB, user_emb, item_id, (float*)d_out);
    spmm_mid_kernel<<<SPMM_BLOCKS_H, 256>>>(rp, ecv, hB, hC);
    spmm_last_kernel<<<SPMM_BLOCKS_H, 256>>>(rp, ecv, hA, hB, hC,
                                             (float*)d_out);
}

// round 15
// speedup vs baseline: 1.0806x; 1.0377x over previous
#include <cuda_runtime.h>
#include <cuda_fp16.h>
#include <cstdint>

#define NUM_USERS  100000
#define NUM_ITEMS  50000
#define NUM_BRANDS 1000
#define NTOT       (NUM_USERS + NUM_ITEMS + NUM_BRANDS)   // 151000
#define DIM        64
#define DCONT      384
#define KDIM       (DIM + DCONT)                          // 448
#define NDF        (NTOT * DIM)
#define ND4        (NDF / 4)
#define ND8        (NDF / 8)
#define UD4        (NUM_USERS * DIM / 4)
#define ID4        ((NUM_ITEMS * DIM) / 4)
#define UD8        (NUM_USERS * DIM / 8)
#define BR8        ((NUM_BRANDS * DIM) / 8)
#define INIT8      (UD8 + BR8)
#define ECHO4      (UD4 + ID4)                             // 2,400,000
#define EMAX       4800000
#define SCAN_CHUNK 1024
#define SCAN_NBLK  ((NTOT + SCAN_CHUNK - 1) / SCAN_CHUNK)  // 148

#define BM 128
#define BN 64
#define BK 16
#define GEMM_BLOCKS ((NUM_ITEMS + BM - 1) / BM)            // 391

// Scratch: half-precision node feature buffers stored as uint4 (8 halves).
__device__ uint4 g_hA[ND8];   // ego
__device__ uint4 g_hB[ND8];   // y1
__device__ uint4 g_hC[ND8];   // y2
__device__ int   g_rowptr[NTOT + 1];
__device__ int   g_cnt[NTOT];          // hist counts, then cursor for scatter
__device__ int2  g_ecv[EMAX];          // packed (col, val_bits fp32)
__device__ int   g_bsum[SCAN_NBLK];

// ---------- packed f32x2 helpers ----------
__device__ __forceinline__ unsigned long long pack2(float lo, float hi) {
    unsigned long long r;
    asm("mov.b64 %0, {%1, %2};" : "=l"(r) : "f"(lo), "f"(hi));
    return r;
}
__device__ __forceinline__ void fma2(unsigned long long& d,
                                     unsigned long long a,
                                     unsigned long long b) {
    asm("fma.rn.f32x2 %0, %1, %2, %0;" : "+l"(d) : "l"(a), "l"(b));
}
__device__ __forceinline__ void add2(unsigned long long& d,
                                     unsigned long long a) {
    asm("add.rn.f32x2 %0, %0, %1;" : "+l"(d) : "l"(a));
}
__device__ __forceinline__ float2 unpack2(unsigned long long v) {
    float2 r;
    asm("mov.b64 {%0, %1}, %2;" : "=f"(r.x), "=f"(r.y) : "l"(v));
    return r;
}

__device__ __forceinline__ uint4 f8_to_h8(const float* o) {
    uint4 r;
    __half2* h = reinterpret_cast<__half2*>(&r);
    h[0] = __floats2half2_rn(o[0], o[1]);
    h[1] = __floats2half2_rn(o[2], o[3]);
    h[2] = __floats2half2_rn(o[4], o[5]);
    h[3] = __floats2half2_rn(o[6], o[7]);
    return r;
}

// ---------------------------------------------------------------------------
// GEMM device path (R8, unchanged)
// ---------------------------------------------------------------------------
__device__ void gemm_path(int gblk, int tid,
                          const float* __restrict__ id_emb,
                          const float* __restrict__ content,
                          const float* __restrict__ W,
                          const float* __restrict__ bias,
                          uint4* __restrict__ hA,
                          float* smem_raw) {
    float (*As)[BM + 4] = reinterpret_cast<float (*)[BM + 4]>(smem_raw);
    float (*Ws)[BN + 4] = reinterpret_cast<float (*)[BN + 4]>(smem_raw + BK * (BM + 4));

    const int tx = tid & 7;
    const int ty = tid >> 3;
    const int block_row = gblk * BM;

    unsigned long long acc2[2][8];
#pragma unroll
    for (int p = 0; p < 2; p++)
#pragma unroll
        for (int j = 0; j < 8; j++) acc2[p][j] = 0ULL;

    for (int k0 = 0; k0 < KDIM; k0 += BK) {
#pragma unroll
        for (int i = 0; i < 2; i++) {
            int lin = tid + i * 256;
            int r = lin >> 2;
            int kq = (lin & 3) * 4;
            int gr = block_row + r;
            float4 v = make_float4(0.f, 0.f, 0.f, 0.f);
            if (gr < NUM_ITEMS) {
                int gk = k0 + kq;
                v = (gk < DIM)
                  ? *reinterpret_cast<const float4*>(id_emb + (size_t)gr * DIM + gk)
                  : *reinterpret_cast<const float4*>(content + (size_t)gr * DCONT + (gk - DIM));
            }
            As[kq + 0][r] = v.x;
            As[kq + 1][r] = v.y;
            As[kq + 2][r] = v.z;
            As[kq + 3][r] = v.w;
        }
        {
            int j = tid >> 2;
            int kq = (tid & 3) * 4;
            float4 v = *reinterpret_cast<const float4*>(W + (size_t)j * KDIM + k0 + kq);
            Ws[kq + 0][j] = v.x;
            Ws[kq + 1][j] = v.y;
            Ws[kq + 2][j] = v.z;
            Ws[kq + 3][j] = v.w;
        }
        __syncthreads();

#pragma unroll
        for (int k = 0; k < BK; k++) {
            float4 a4 = *reinterpret_cast<const float4*>(&As[k][ty * 4]);
            unsigned long long a2[2];
            a2[0] = pack2(a4.x, a4.y);
            a2[1] = pack2(a4.z, a4.w);
            float4 w0 = *reinterpret_cast<const float4*>(&Ws[k][tx * 8]);
            float4 w1 = *reinterpret_cast<const float4*>(&Ws[k][tx * 8 + 4]);
            unsigned long long wb[8];
            wb[0] = pack2(w0.x, w0.x); wb[1] = pack2(w0.y, w0.y);
            wb[2] = pack2(w0.z, w0.z); wb[3] = pack2(w0.w, w0.w);
            wb[4] = pack2(w1.x, w1.x); wb[5] = pack2(w1.y, w1.y);
            wb[6] = pack2(w1.z, w1.z); wb[7] = pack2(w1.w, w1.w);
#pragma unroll
            for (int p = 0; p < 2; p++)
#pragma unroll
                for (int j = 0; j < 8; j++) fma2(acc2[p][j], a2[p], wb[j]);
        }
        __syncthreads();
    }

    float4 b0 = *reinterpret_cast<const float4*>(bias + tx * 8);
    float4 b1 = *reinterpret_cast<const float4*>(bias + tx * 8 + 4);
    float bcol[8] = {b0.x, b0.y, b0.z, b0.w, b1.x, b1.y, b1.z, b1.w};

#pragma unroll
    for (int r = 0; r < 4; r++) {
        int gr = block_row + ty * 4 + r;
        if (gr >= NUM_ITEMS) continue;
        int p = r >> 1;
        float o[8];
#pragma unroll
        for (int j = 0; j < 8; j++) {
            float2 u = unpack2(acc2[p][j]);
            float v = ((r & 1) ? u.y : u.x) + bcol[j];
            o[j] = (v > 0.f) ? v : 0.01f * v;
        }
        hA[(size_t)(NUM_USERS + gr) * 8 + tx] = f8_to_h8(o);
    }
}

// ---------------------------------------------------------------------------
// K1 mega: [0,G) gemm | [G,G+H) hist | rest: fp32->fp16 user/brand init
// ---------------------------------------------------------------------------
__global__ __launch_bounds__(256)
void mega1_kernel(const float* __restrict__ id_emb,
                  const float* __restrict__ content,
                  const float* __restrict__ W,
                  const float* __restrict__ bias,
                  const float* __restrict__ user_emb,
                  const float* __restrict__ brand,
                  const int*   __restrict__ rows, int E, int histBlocks,
                  int* __restrict__ cnt,
                  uint4* __restrict__ hA) {
    __shared__ float smem_raw[BK * (BM + 4) + BK * (BN + 4)];
    int b = blockIdx.x;
    int tid = threadIdx.x;

    if (b < GEMM_BLOCKS) {
        gemm_path(b, tid, id_emb, content, W, bias, hA, smem_raw);
        return;
    }
    b -= GEMM_BLOCKS;
    if (b < histBlocks) {
        int base = (b * 256 + tid) * 4;
        if (base + 4 <= E) {
            int4 r = *reinterpret_cast<const int4*>(rows + base);
            atomicAdd(&cnt[r.x], 1);
            atomicAdd(&cnt[r.y], 1);
            atomicAdd(&cnt[r.z], 1);
            atomicAdd(&cnt[r.w], 1);
        } else {
            for (int j = base; j < E; j++) atomicAdd(&cnt[rows[j]], 1);
        }
        return;
    }
    b -= histBlocks;
    int idx = b * 256 + tid;
    if (idx >= INIT8) return;
    const float* src;
    size_t dst;
    if (idx < UD8) { src = user_emb + (size_t)idx * 8; dst = idx; }
    else {
        src = brand + (size_t)(idx - UD8) * 8;
        dst = (size_t)(NUM_USERS + NUM_ITEMS) * 8 + (idx - UD8);
    }
    float4 f0 = *reinterpret_cast<const float4*>(src);
    float4 f1 = *reinterpret_cast<const float4*>(src + 4);
    float o[8] = {f0.x, f0.y, f0.z, f0.w, f1.x, f1.y, f1.z, f1.w};
    hA[dst] = f8_to_h8(o);
}

// ---------------------------------------------------------------------------
// CSR scan
// ---------------------------------------------------------------------------
__global__ void scan_partial_kernel(const int* __restrict__ cnt,
                                    int* __restrict__ bsum) {
    __shared__ int s[256];
    int b = blockIdx.x, t = threadIdx.x;
    int base = b * SCAN_CHUNK + t * 4;
    int v = 0;
#pragma unroll
    for (int j = 0; j < 4; j++) {
        int idx = base + j;
        if (idx < NTOT) v += cnt[idx];
    }
    s[t] = v;
    __syncthreads();
    for (int off = 128; off > 0; off >>= 1) {
        if (t < off) s[t] += s[t + off];
        __syncthreads();
    }
    if (t == 0) bsum[b] = s[0];
}

__global__ void write_rowptr_kernel(const int* __restrict__ cnt,
                                    const int* __restrict__ bsum,
                                    int* __restrict__ rp,
                                    int* __restrict__ cur, int E) {
    __shared__ int sb[256];
    __shared__ int s[256];
    int b = blockIdx.x, t = threadIdx.x;

    int bv = (t < SCAN_NBLK) ? bsum[t] : 0;
    sb[t] = bv;
    __syncthreads();
    for (int off = 1; off < 256; off <<= 1) {
        int tmp = (t >= off) ? sb[t - off] : 0;
        __syncthreads();
        sb[t] += tmp;
        __syncthreads();
    }
    int boff_b = sb[b] - bsum[b];
    __syncthreads();

    int base = b * SCAN_CHUNK + t * 4;
    int loc4[4];
    int v = 0;
#pragma unroll
    for (int j = 0; j < 4; j++) {
        int idx = base + j;
        loc4[j] = (idx < NTOT) ? cnt[idx] : 0;
        v += loc4[j];
    }
    s[t] = v;
    __syncthreads();
    for (int off = 1; off < 256; off <<= 1) {
        int tmp = (t >= off) ? s[t - off] : 0;
        __syncthreads();
        s[t] += tmp;
        __syncthreads();
    }
    int run = s[t] - v + boff_b;
#pragma unroll
    for (int j = 0; j < 4; j++) {
        int idx = base + j;
        if (idx < NTOT) { rp[idx] = run; cur[idx] = run; }
        run += loc4[j];
    }
    if (b == 0 && t == 0) rp[NTOT] = E;
}

// Scatter with atomic cursor, 4 edges/thread (R8-measured best).
__global__ void scatter_kernel(const int* __restrict__ rows,
                               const int* __restrict__ cols,
                               const float* __restrict__ vals, int E,
                               int* __restrict__ cur,
                               long long* __restrict__ ecv) {
    int i = blockIdx.x * blockDim.x + threadIdx.x;
    int base = i * 4;
    if (base + 4 <= E) {
        int4   r = *reinterpret_cast<const int4*>(rows + base);
        int4   c = *reinterpret_cast<const int4*>(cols + base);
        float4 v = *reinterpret_cast<const float4*>(vals + base);
        int p;
        p = atomicAdd(&cur[r.x], 1);
        ecv[p] = ((long long)__float_as_int(v.x) << 32) | (unsigned int)c.x;
        p = atomicAdd(&cur[r.y], 1);
        ecv[p] = ((long long)__float_as_int(v.y) << 32) | (unsigned int)c.y;
        p = atomicAdd(&cur[r.z], 1);
        ecv[p] = ((long long)__float_as_int(v.z) << 32) | (unsigned int)c.z;
        p = atomicAdd(&cur[r.w], 1);
        ecv[p] = ((long long)__float_as_int(v.w) << 32) | (unsigned int)c.w;
    } else {
        for (int j = base; j < E; j++) {
            int p = atomicAdd(&cur[rows[j]], 1);
            ecv[p] = ((long long)__float_as_int(vals[j]) << 32) | (unsigned int)cols[j];
        }
    }
}

// ---------------------------------------------------------------------------
// fp16 CSR SpMM: 8 lanes/row, uint4 per lane. 4-edge blocks accumulate in
// fp16 (HMUL2/HFMA2 — no per-edge conversions), flushed into packed-fp32
// accumulators per block. Tail edges use the fp32-convert path.
// ---------------------------------------------------------------------------
struct F8acc { float2 a, b, c, d; };

__device__ __forceinline__ void fma_h8_x2(unsigned long long& a0,
                                          unsigned long long& a1,
                                          unsigned long long& a2,
                                          unsigned long long& a3,
                                          unsigned long long v2, uint4 x) {
    const __half2* h = reinterpret_cast<const __half2*>(&x);
    float2 f0 = __half22float2(h[0]);
    float2 f1 = __half22float2(h[1]);
    float2 f2 = __half22float2(h[2]);
    float2 f3 = __half22float2(h[3]);
    fma2(a0, pack2(f0.x, f0.y), v2);
    fma2(a1, pack2(f1.x, f1.y), v2);
    fma2(a2, pack2(f2.x, f2.y), v2);
    fma2(a3, pack2(f3.x, f3.y), v2);
}

__device__ __forceinline__ F8acc spmm_row_h(const int* __restrict__ rp,
                                            const int2* __restrict__ ecv,
                                            const uint4* __restrict__ X,
                                            int row, int lane) {
    int s = __ldg(rp + row), e = __ldg(rp + row + 1);
    unsigned long long a0 = 0ULL, a1 = 0ULL, a2 = 0ULL, a3 = 0ULL;
    int i = s;
    for (; i + 4 <= e; i += 4) {
        int2 c0 = __ldg(ecv + i),     c1 = __ldg(ecv + i + 1);
        int2 c2 = __ldg(ecv + i + 2), c3 = __ldg(ecv + i + 3);
        uint4 x0 = __ldg(X + (size_t)c0.x * 8 + lane);
        uint4 x1 = __ldg(X + (size_t)c1.x * 8 + lane);
        uint4 x2 = __ldg(X + (size_t)c2.x * 8 + lane);
        uint4 x3 = __ldg(X + (size_t)c3.x * 8 + lane);
        __half2 vh0 = __float2half2_rn(__int_as_float(c0.y));
        __half2 vh1 = __float2half2_rn(__int_as_float(c1.y));
        __half2 vh2 = __float2half2_rn(__int_as_float(c2.y));
        __half2 vh3 = __float2half2_rn(__int_as_float(c3.y));
        const __half2* h0 = reinterpret_cast<const __half2*>(&x0);
        const __half2* h1 = reinterpret_cast<const __half2*>(&x1);
        const __half2* h2 = reinterpret_cast<const __half2*>(&x2);
        const __half2* h3 = reinterpret_cast<const __half2*>(&x3);
        // fp16 partial over this 4-edge block (no conversions in the hot path)
        __half2 q0 = __hmul2(h0[0], vh0);
        __half2 q1 = __hmul2(h0[1], vh0);
        __half2 q2 = __hmul2(h0[2], vh0);
        __half2 q3 = __hmul2(h0[3], vh0);
        q0 = __hfma2(h1[0], vh1, q0);
        q1 = __hfma2(h1[1], vh1, q1);
        q2 = __hfma2(h1[2], vh1, q2);
        q3 = __hfma2(h1[3], vh1, q3);
        q0 = __hfma2(h2[0], vh2, q0);
        q1 = __hfma2(h2[1], vh2, q1);
        q2 = __hfma2(h2[2], vh2, q2);
        q3 = __hfma2(h2[3], vh2, q3);
        q0 = __hfma2(h3[0], vh3, q0);
        q1 = __hfma2(h3[1], vh3, q1);
        q2 = __hfma2(h3[2], vh3, q2);
        q3 = __hfma2(h3[3], vh3, q3);
        // flush partial into fp32 packed accumulators
        float2 f0 = __half22float2(q0);
        float2 f1 = __half22float2(q1);
        float2 f2 = __half22float2(q2);
        float2 f3 = __half22float2(q3);
        add2(a0, pack2(f0.x, f0.y));
        add2(a1, pack2(f1.x, f1.y));
        add2(a2, pack2(f2.x, f2.y));
        add2(a3, pack2(f3.x, f3.y));
    }
    for (; i < e; i++) {
        int2 ee = __ldg(ecv + i);
        uint4 xv = __ldg(X + (size_t)ee.x * 8 + lane);
        float v = __int_as_float(ee.y);
        fma_h8_x2(a0, a1, a2, a3, pack2(v, v), xv);
    }
    F8acc acc;
    acc.a = unpack2(a0);
    acc.b = unpack2(a1);
    acc.c = unpack2(a2);
    acc.d = unpack2(a3);
    return acc;
}

__device__ __forceinline__ uint4 acc_to_h8(const F8acc& acc) {
    uint4 r;
    __half2* h = reinterpret_cast<__half2*>(&r);
    h[0] = __float22half2_rn(acc.a);
    h[1] = __float22half2_rn(acc.b);
    h[2] = __float22half2_rn(acc.c);
    h[3] = __float22half2_rn(acc.d);
    return r;
}

#define SPMM_BLOCKS_H ((NTOT * 8 + 255) / 256)
#define ECHO_BLOCKS   ((ECHO4 + 255) / 256)

// Layer 1 (+ echo copies folded in — R8 placement, measured best)
__global__ __launch_bounds__(256, 6)
void spmm1_mega_kernel(const int* __restrict__ rp,
                       const int2* __restrict__ ecv,
                       const uint4* __restrict__ X,
                       uint4* __restrict__ Y,
                       const float* __restrict__ user_emb,
                       const float* __restrict__ item_id,
                       float* __restrict__ out) {
    int b = blockIdx.x;
    int tid = threadIdx.x;
    if (b < SPMM_BLOCKS_H) {
        int g = b * 256 + tid;
        int row = g >> 3;
        int lane = g & 7;
        if (row >= NTOT) return;
        F8acc a = spmm_row_h(rp, ecv, X, row, lane);
        Y[(size_t)row * 8 + lane] = acc_to_h8(a);
        return;
    }
    b -= SPMM_BLOCKS_H;
    int idx = b * 256 + tid;
    if (idx >= ECHO4) return;
    float4 v = (idx < UD4)
             ? reinterpret_cast<const float4*>(user_emb)[idx]
             : reinterpret_cast<const float4*>(item_id)[idx - UD4];
    reinterpret_cast<float4*>(out)[ND4 + idx] = v;
}

// Layer 2
__global__ __launch_bounds__(256, 6)
void spmm_mid_kernel(const int* __restrict__ rp,
                     const int2* __restrict__ ecv,
                     const uint4* __restrict__ X,
                     uint4* __restrict__ Y) {
    int g = blockIdx.x * blockDim.x + threadIdx.x;
    int row = g >> 3;
    int lane = g & 7;
    if (row >= NTOT) return;
    F8acc a = spmm_row_h(rp, ecv, X, row, lane);
    Y[(size_t)row * 8 + lane] = acc_to_h8(a);
}

// Layer 3 fused finalize: out = (A + B + C + spmm(C)) * 0.25, fp32 out.
__global__ __launch_bounds__(256, 6)
void spmm_last_kernel(const int* __restrict__ rp,
                      const int2* __restrict__ ecv,
                      const uint4* __restrict__ hA,
                      const uint4* __restrict__ hB,
                      const uint4* __restrict__ hC,
                      float* __restrict__ out) {
    int g = blockIdx.x * blockDim.x + threadIdx.x;
    int row = g >> 3;
    int lane = g & 7;
    if (row >= NTOT) return;
    F8acc a = spmm_row_h(rp, ecv, hC, row, lane);
    size_t o8 = (size_t)row * 8 + lane;
    uint4 ua = __ldg(hA + o8);
    uint4 ub = __ldg(hB + o8);
    uint4 uc = __ldg(hC + o8);
    const __half2* ha = reinterpret_cast<const __half2*>(&ua);
    const __half2* hb = reinterpret_cast<const __half2*>(&ub);
    const __half2* hc = reinterpret_cast<const __half2*>(&uc);
    float res[8];
    float2* ap = reinterpret_cast<float2*>(&a);
#pragma unroll
    for (int q = 0; q < 4; q++) {
        float2 fa = __half22float2(ha[q]);
        float2 fb = __half22float2(hb[q]);
        float2 fc = __half22float2(hc[q]);
        res[q * 2 + 0] = (fa.x + fb.x + fc.x + ap[q].x) * 0.25f;
        res[q * 2 + 1] = (fa.y + fb.y + fc.y + ap[q].y) * 0.25f;
    }
    size_t base = (size_t)row * DIM + lane * 8;
    *reinterpret_cast<float4*>(out + base)     = make_float4(res[0], res[1], res[2], res[3]);
    *reinterpret_cast<float4*>(out + base + 4) = make_float4(res[4], res[5], res[6], res[7]);
}

// ---------------------------------------------------------------------------
extern "C" void kernel_launch(void* const* d_in, const int* in_sizes, int n_in,
                              void* d_out, int out_size) {
    const int*   edge_row = (const int*)  d_in[0];
    const int*   edge_col = (const int*)  d_in[1];
    const float* edge_val = (const float*)d_in[2];
    const float* user_emb = (const float*)d_in[3];
    const float* item_id  = (const float*)d_in[4];
    const float* brand    = (const float*)d_in[5];
    const float* content  = (const float*)d_in[6];
    const float* fusion_W = (const float*)d_in[7];
    const float* fusion_b = (const float*)d_in[8];
    const int E = in_sizes[0];

    uint4 *hA, *hB, *hC;
    int *rp, *cnt, *bsum;
    int2 *ecv;
    cudaGetSymbolAddress((void**)&hA,   g_hA);
    cudaGetSymbolAddress((void**)&hB,   g_hB);
    cudaGetSymbolAddress((void**)&hC,   g_hC);
    cudaGetSymbolAddress((void**)&rp,   g_rowptr);
    cudaGetSymbolAddress((void**)&cnt,  g_cnt);
    cudaGetSymbolAddress((void**)&ecv,  g_ecv);
    cudaGetSymbolAddress((void**)&bsum, g_bsum);

    cudaMemsetAsync(cnt, 0, NTOT * sizeof(int));

    // K1: GEMM + hist + fp16 init
    int histBlocks = ((E + 3) / 4 + 255) / 256;
    int initBlocks = (INIT8 + 255) / 256;
    mega1_kernel<<<GEMM_BLOCKS + histBlocks + initBlocks, 256>>>(
        item_id, content, fusion_W, fusion_b, user_emb, brand,
        edge_row, E, histBlocks, cnt, hA);

    scan_partial_kernel<<<SCAN_NBLK, 256>>>(cnt, bsum);
    write_rowptr_kernel<<<SCAN_NBLK, 256>>>(cnt, bsum, rp, cnt, E);
    scatter_kernel<<<((E + 3) / 4 + 255) / 256, 256>>>(
        edge_row, edge_col, edge_val, E, cnt, (long long*)ecv);

    // Propagation: fp16 storage, fp16 4-edge partials, fp32 accumulation
    spmm1_mega_kernel<<<SPMM_BLOCKS_H + ECHO_BLOCKS, 256>>>(
        rp, ecv, hA, hB, user_emb, item_id, (float*)d_out);
    spmm_mid_kernel<<<SPMM_BLOCKS_H, 256>>>(rp, ecv, hB, hC);
    spmm_last_kernel<<<SPMM_BLOCKS_H, 256>>>(rp, ecv, hA, hB, hC,
                                             (float*)d_out);
}